// round 4
// baseline (speedup 1.0000x reference)
#include <cuda_runtime.h>
#include <cuda_bf16.h>
#include <cstddef>

#define BQ 8192
#define NQ 784
#define NSITES 782          // cores_mid count
#define NSTEP 391           // steps per half-chain
#define WARPS_FWD 1366      // ceil(8192 / 6 chains-per-warp)
#define NBLOCKS 683         // 2*1366 warps / 4 warps-per-block

typedef unsigned long long ull;

// Scratch
__device__ float2     g_feat[(size_t)NQ * BQ];        // [site][batch] (cos,sin)
__device__ ulonglong2 g_packF[(size_t)NSITES * 50];   // forward cols:  (site*5+p)*10 u2
__device__ ulonglong2 g_packR[(size_t)NSITES * 50];   // backward cols (transposed)
__device__ ull        g_V[(size_t)BQ * 5];            // forward half result (pairs)
__device__ ull        g_U[(size_t)BQ * 5];            // backward half result (pairs)

// ---------------- packed f32x2 helpers ----------------
__device__ __forceinline__ ull pack2(float lo, float hi) {
    ull r;
    asm("mov.b64 %0, {%1, %2};" : "=l"(r)
        : "r"(__float_as_uint(lo)), "r"(__float_as_uint(hi)));
    return r;
}
__device__ __forceinline__ float2 unpack2(ull v) {
    unsigned int lo, hi;
    asm("mov.b64 {%0, %1}, %2;" : "=r"(lo), "=r"(hi) : "l"(v));
    return make_float2(__uint_as_float(lo), __uint_as_float(hi));
}
__device__ __forceinline__ ull fma2(ull a, ull b, ull c) {
    ull d;
    asm("fma.rn.f32x2 %0, %1, %2, %3;" : "=l"(d) : "l"(a), "l"(b), "l"(c));
    return d;
}
__device__ __forceinline__ ull mul2(ull a, ull b) {
    ull d;
    asm("mul.rn.f32x2 %0, %1, %2;" : "=l"(d) : "l"(a), "l"(b));
    return d;
}
__device__ __forceinline__ ull add2(ull a, ull b) {
    ull d;
    asm("add.rn.f32x2 %0, %1, %2;" : "=l"(d) : "l"(a), "l"(b));
    return d;
}

// ---------------------------------------------------------------------------
// K1: featurize + transpose. x:(B,N) -> g_feat:(N,B) float2 (cos, sin)
// ---------------------------------------------------------------------------
__global__ void feat_kernel(const float* __restrict__ x) {
    __shared__ float2 tf[32][33];
    const int tx = threadIdx.x;
    const int ty = threadIdx.y;
    const int n0 = blockIdx.x * 32;
    const int b0 = blockIdx.y * 32;

    #pragma unroll
    for (int j = 0; j < 32; j += 8) {
        int n = n0 + tx;
        int b = b0 + ty + j;
        if (n < NQ) {
            float val = x[(size_t)b * NQ + n];
            float s, c;
            sincospif(val, &s, &c);
            tf[tx][ty + j] = make_float2(c, s);
        }
    }
    __syncthreads();
    #pragma unroll
    for (int j = 0; j < 32; j += 8) {
        int n = n0 + ty + j;
        int b = b0 + tx;
        if (n < NQ) g_feat[(size_t)n * BQ + b] = tf[ty + j][tx];
    }
}

// ---------------------------------------------------------------------------
// K1b: repack cores.
// src[site][l][d][r], 200 floats/site.
// packF per (site,p): 10 u2 = [d0: lp=0..4][d1: lp=0..4]
//   u2 float k (0..3): l = 2*lp + (k>>1), r = 2*p + (k&1)
//   (i.e. u2.x = (M_d[2lp][2p], M_d[2lp][2p+1]), u2.y = same for l=2lp+1)
// packR: transposed roles:  l = 2*p + (k&1), r = 2*lp + (k>>1)
// ---------------------------------------------------------------------------
__global__ void prep_kernel(const float* __restrict__ src) {
    const int site = blockIdx.x;
    const int o = threadIdx.x;           // 0..199
    const int p   = o / 40;
    const int rem = o % 40;
    const int d   = rem / 20;
    const int lp  = (rem % 20) / 4;
    const int k   = rem % 4;
    const float* s = src + (size_t)site * 200;
    {
        int l = 2 * lp + (k >> 1), r = 2 * p + (k & 1);
        ((float*)g_packF)[(size_t)site * 200 + o] = s[l * 20 + d * 10 + r];
    }
    {
        int l = 2 * p + (k & 1), r = 2 * lp + (k >> 1);
        ((float*)g_packR)[(size_t)site * 200 + o] = s[l * 20 + d * 10 + r];
    }
}

// ---------------------------------------------------------------------------
// One step of the split chain (shared by fwd/bwd; layout differences absorbed
// by packF/packR). Lane holds output pair in (vx, vy).
// ---------------------------------------------------------------------------
__device__ __forceinline__ void split_step(const ulonglong2* __restrict__ mat,
                                           float2 f, int c5,
                                           float& vx, float& vy) {
    // exchange the 10-element state within the chain's 5 lanes
    float ex[10];
    #pragma unroll
    for (int j = 0; j < 5; j++) {
        ex[2 * j]     = __shfl_sync(0xffffffffu, vx, c5 + j);
        ex[2 * j + 1] = __shfl_sync(0xffffffffu, vy, c5 + j);
    }
    ull E[10];
    #pragma unroll
    for (int l = 0; l < 10; l++) E[l] = pack2(ex[l], ex[l]);

    const ulonglong2 A0 = __ldg(mat + 0), A1 = __ldg(mat + 1), A2 = __ldg(mat + 2),
                     A3 = __ldg(mat + 3), A4 = __ldg(mat + 4);
    ull a0 = mul2(E[0], A0.x);
    ull a1 = mul2(E[1], A0.y);
    a0 = fma2(E[2], A1.x, a0);  a1 = fma2(E[3], A1.y, a1);
    a0 = fma2(E[4], A2.x, a0);  a1 = fma2(E[5], A2.y, a1);
    a0 = fma2(E[6], A3.x, a0);  a1 = fma2(E[7], A3.y, a1);
    a0 = fma2(E[8], A4.x, a0);  a1 = fma2(E[9], A4.y, a1);

    const ulonglong2 B0 = __ldg(mat + 5), B1 = __ldg(mat + 6), B2 = __ldg(mat + 7),
                     B3 = __ldg(mat + 8), B4 = __ldg(mat + 9);
    ull c0 = mul2(E[0], B0.x);
    ull c1 = mul2(E[1], B0.y);
    c0 = fma2(E[2], B1.x, c0);  c1 = fma2(E[3], B1.y, c1);
    c0 = fma2(E[4], B2.x, c0);  c1 = fma2(E[5], B2.y, c1);
    c0 = fma2(E[6], B3.x, c0);  c1 = fma2(E[7], B3.y, c1);
    c0 = fma2(E[8], B4.x, c0);  c1 = fma2(E[9], B4.y, c1);

    const ull fc2 = pack2(f.x, f.x);
    const ull fs2 = pack2(f.y, f.y);
    const ull vp = fma2(fs2, add2(c0, c1), mul2(fc2, add2(a0, a1)));
    float2 vv = unpack2(vp);
    vx = vv.x; vy = vv.y;
}

// ---------------------------------------------------------------------------
// K2: split chain. Warp = 6 chain-halves x 5 lanes (lanes 30,31 duplicate
// chain 0 and never store). Warps [0,1366) forward, [1366,2732) backward.
// ---------------------------------------------------------------------------
__global__ __launch_bounds__(128, 5)
void chain_kernel(const float* __restrict__ core_first,
                  const float* __restrict__ core_last) {
    const int lane = threadIdx.x & 31;
    const int w = (blockIdx.x * blockDim.x + threadIdx.x) >> 5;

    int c = lane / 5;                   // chain-in-warp 0..5 (6 for lanes 30,31)
    int p = lane - c * 5;
    const bool active = (lane < 30);
    if (!active) { c = 0; p = lane - 30; }
    const int c5 = c * 5;

    const bool fwd = (w < WARPS_FWD);
    const int b_raw = (fwd ? w : (w - WARPS_FWD)) * 6 + c;
    const bool store_ok = active && (b_raw < BQ);
    const int b = (b_raw < BQ) ? b_raw : (BQ - 1);

    float vx, vy;

    if (fwd) {
        // init: v[l] = c0*cf[0][l] + s0*cf[1][l], pair (2p, 2p+1)
        const float2 f0 = g_feat[b];
        const float* cf = core_first;
        vx = f0.x * __ldg(cf + 2 * p)     + f0.y * __ldg(cf + 10 + 2 * p);
        vy = f0.x * __ldg(cf + 2 * p + 1) + f0.y * __ldg(cf + 10 + 2 * p + 1);

        const ulonglong2* mat = g_packF + (size_t)p * 10;   // site 0
        const float2* fp = g_feat + (size_t)BQ + b;         // feature site 1
        for (int k = 0; k < NSTEP; k++) {
            split_step(mat, *fp, c5, vx, vy);
            mat += 50; fp += BQ;
        }
        if (store_ok) g_V[(size_t)b * 5 + p] = pack2(vx, vy);
    } else {
        // init: u[l] = fL.x*cl[l*2] + fL.y*cl[l*2+1], pair l=2p, 2p+1
        const float2 fL = g_feat[(size_t)(NQ - 1) * BQ + b];
        const float* cl = core_last;
        vx = fL.x * __ldg(cl + 4 * p)     + fL.y * __ldg(cl + 4 * p + 1);
        vy = fL.x * __ldg(cl + 4 * p + 2) + fL.y * __ldg(cl + 4 * p + 3);

        const ulonglong2* mat = g_packR + ((size_t)(NSITES - 1) * 5 + p) * 10; // site idx 781
        const float2* fp = g_feat + (size_t)(NQ - 2) * BQ + b;                 // feature site 782
        for (int k = 0; k < NSTEP; k++) {
            split_step(mat, *fp, c5, vx, vy);
            mat -= 50; fp -= BQ;
        }
        if (store_ok) g_U[(size_t)b * 5 + p] = pack2(vx, vy);
    }
}

// ---------------------------------------------------------------------------
// K3: s[b] = dot(v,u);  logits[b,c] = s[b] * sum_d OT[c,d,0]
// ---------------------------------------------------------------------------
__global__ void combine_kernel(const float* __restrict__ ot,
                               float* __restrict__ out) {
    const int b = blockIdx.x * blockDim.x + threadIdx.x;
    if (b >= BQ) return;
    float s = 0.f;
    #pragma unroll
    for (int j = 0; j < 5; j++) {
        float2 a = unpack2(g_V[(size_t)b * 5 + j]);
        float2 u = unpack2(g_U[(size_t)b * 5 + j]);
        s += a.x * u.x + a.y * u.y;
    }
    #pragma unroll
    for (int c = 0; c < 10; c++) {
        float w = 0.f;
        #pragma unroll
        for (int d = 0; d < 10; d++) w += __ldg(ot + c * 10 + d);
        out[(size_t)b * 10 + c] = s * w;
    }
}

// ---------------------------------------------------------------------------
extern "C" void kernel_launch(void* const* d_in, const int* in_sizes, int n_in,
                              void* d_out, int out_size) {
    const float* x          = (const float*)d_in[0];  // (8192, 784)
    const float* core_first = (const float*)d_in[1];  // (1, 2, 10)
    const float* cores_mid  = (const float*)d_in[2];  // (782, 10, 2, 10)
    const float* core_last  = (const float*)d_in[3];  // (10, 2, 1)
    const float* out_t      = (const float*)d_in[4];  // (10, 10, 1)
    float* out = (float*)d_out;                       // (8192, 10)

    dim3 fgrid((NQ + 31) / 32, BQ / 32);
    dim3 fblk(32, 8);
    feat_kernel<<<fgrid, fblk>>>(x);
    prep_kernel<<<NSITES, 200>>>(cores_mid);

    chain_kernel<<<NBLOCKS, 128>>>(core_first, core_last);

    combine_kernel<<<BQ / 128, 128>>>(out_t, out);
}

// round 5
// speedup vs baseline: 2.1539x; 2.1539x over previous
#include <cuda_runtime.h>
#include <cuda_bf16.h>
#include <cstddef>
#include <cstdint>

#define BQ 8192
#define NQ 784
#define NSITES 782
#define MIDQ 392
#define NSTEP 391          // steps per half-chain
#define RING 4             // smem stages per warp
#define DIST 3             // prefetch distance (sites ahead)

typedef unsigned long long ull;

// Scratch
__device__ float2     g_feat[(size_t)NQ * BQ];         // [site][batch] (cos,sin)
__device__ ulonglong2 g_coresT[(size_t)NSITES * 50];   // transposed cores (backward)
__device__ ull        g_V[(size_t)BQ * 5];
__device__ ull        g_U[(size_t)BQ * 5];

// ---------------- packed f32x2 helpers ----------------
__device__ __forceinline__ ull pack2(float lo, float hi) {
    ull r;
    asm("mov.b64 %0, {%1, %2};" : "=l"(r)
        : "r"(__float_as_uint(lo)), "r"(__float_as_uint(hi)));
    return r;
}
__device__ __forceinline__ float2 unpack2(ull v) {
    unsigned int lo, hi;
    asm("mov.b64 {%0, %1}, %2;" : "=r"(lo), "=r"(hi) : "l"(v));
    return make_float2(__uint_as_float(lo), __uint_as_float(hi));
}
__device__ __forceinline__ ull fma2(ull a, ull b, ull c) {
    ull d;
    asm("fma.rn.f32x2 %0, %1, %2, %3;" : "=l"(d) : "l"(a), "l"(b), "l"(c));
    return d;
}
__device__ __forceinline__ ull mul2(ull a, ull b) {
    ull d;
    asm("mul.rn.f32x2 %0, %1, %2;" : "=l"(d) : "l"(a), "l"(b));
    return d;
}

// ---------------- cp.async helpers ----------------
__device__ __forceinline__ void cp16(uint32_t saddr, const void* gptr) {
    asm volatile("cp.async.cg.shared.global [%0], [%1], 16;"
                 :: "r"(saddr), "l"(gptr) : "memory");
}
__device__ __forceinline__ void cp_commit() {
    asm volatile("cp.async.commit_group;" ::: "memory");
}
template <int N> __device__ __forceinline__ void cp_wait() {
    asm volatile("cp.async.wait_group %0;" :: "n"(N) : "memory");
}

// ---------------------------------------------------------------------------
// K1: featurize + transpose. x:(B,N) -> g_feat:(N,B) float2 (cos, sin)
// ---------------------------------------------------------------------------
__global__ void feat_kernel(const float* __restrict__ x) {
    __shared__ float2 tf[32][33];
    const int tx = threadIdx.x;
    const int ty = threadIdx.y;
    const int n0 = blockIdx.x * 32;
    const int b0 = blockIdx.y * 32;

    #pragma unroll
    for (int j = 0; j < 32; j += 8) {
        int n = n0 + tx;
        int b = b0 + ty + j;
        if (n < NQ) {
            float val = x[(size_t)b * NQ + n];
            float s, c;
            sincospif(val, &s, &c);
            tf[tx][ty + j] = make_float2(c, s);
        }
    }
    __syncthreads();
    #pragma unroll
    for (int j = 0; j < 32; j += 8) {
        int n = n0 + ty + j;
        int b = b0 + tx;
        if (n < NQ) g_feat[(size_t)n * BQ + b] = tf[ty + j][tx];
    }
}

// ---------------------------------------------------------------------------
// K1b: transpose cores for the backward half: src[i][l][d][r] -> dst[i][r][d][l]
// ---------------------------------------------------------------------------
__global__ void transpose_cores(const float* __restrict__ src) {
    const int site = blockIdx.x;
    const int o = threadIdx.x;          // 0..199 : o = r*20 + d*10 + l
    const int r = o / 20;
    const int d = (o % 20) / 10;
    const int l = o % 10;
    ((float*)g_coresT)[(size_t)site * 200 + o] =
        src[(size_t)site * 200 + l * 20 + d * 10 + r];
}

// ---------------------------------------------------------------------------
// K2: per-thread full-r chain with warp-private cp.async smem staging.
// grid=128, block=128 (4 warps). Blocks [0,64): forward; [64,128): backward.
// Each warp stages the 800B site matrix for its direction into its own smem
// ring; matrix reads are broadcast LDS.128; next feature prefetched in reg.
// ---------------------------------------------------------------------------
__global__ __launch_bounds__(128, 1)
void chain_kernel(const float* __restrict__ core_first,
                  const float* __restrict__ cores_mid,
                  const float* __restrict__ core_last) {
    __shared__ __align__(16) char smem[4][RING][800];

    const int tid  = threadIdx.x;
    const int wid  = tid >> 5;
    const int lane = tid & 31;
    const bool fwd = (blockIdx.x < 64);
    const int b = (fwd ? blockIdx.x : blockIdx.x - 64) * 128 + tid;

    // matrix / feature streams
    const char* gsrc;
    long gstep;
    const float2* fp0;
    long fstep;
    if (fwd) {
        gsrc  = (const char*)cores_mid;                      // site 0 ascending
        gstep = 800;
        fp0   = g_feat + (size_t)BQ + b;                     // feature site 1 asc
        fstep = BQ;
    } else {
        gsrc  = (const char*)(g_coresT + (size_t)(NSITES - 1) * 50); // site 781 desc
        gstep = -800;
        fp0   = g_feat + (size_t)(NQ - 2) * BQ + b;          // feature site 782 desc
        fstep = -(long)BQ;
    }

    const uint32_t sbase = (uint32_t)__cvta_generic_to_shared(&smem[wid][0][0]);

    // prologue: prefetch sites 0..DIST-1
    #pragma unroll
    for (int s = 0; s < DIST; s++) {
        const char* g = gsrc + (long)s * gstep;
        uint32_t dst = sbase + s * 800;
        cp16(dst + lane * 16, g + lane * 16);
        if (lane < 18) cp16(dst + (32 + lane) * 16, g + (32 + lane) * 16);
        cp_commit();
    }

    // init state
    ull vp[5];
    if (fwd) {
        const float2 f0 = g_feat[b];
        const ull* cfc = (const ull*)core_first;
        const ull* cfs = (const ull*)(core_first + 10);
        const ull c02 = pack2(f0.x, f0.x);
        const ull s02 = pack2(f0.y, f0.y);
        #pragma unroll
        for (int j = 0; j < 5; j++)
            vp[j] = fma2(s02, __ldg(cfs + j), mul2(c02, __ldg(cfc + j)));
    } else {
        const float2 fL = g_feat[(size_t)(NQ - 1) * BQ + b];
        const float2* cl = (const float2*)core_last;
        #pragma unroll
        for (int j = 0; j < 5; j++) {
            float2 qa = __ldg(cl + 2 * j);
            float2 qb = __ldg(cl + 2 * j + 1);
            vp[j] = pack2(fL.x * qa.x + fL.y * qa.y,
                          fL.x * qb.x + fL.y * qb.y);
        }
    }

    float2 fcur = *fp0;

    for (int k = 0; k < NSTEP; k++) {
        cp_wait<DIST - 1>();          // site k staged
        __syncwarp();

        // prefetch next feature (always in-bounds of g_feat)
        const float2 fnext = fp0[(long)(k + 1) * fstep];

        const ulonglong2* row = (const ulonglong2*)&smem[wid][k & (RING - 1)][0];

        float2 vf0 = unpack2(vp[0]);
        float2 vf1 = unpack2(vp[1]);
        float2 vf2 = unpack2(vp[2]);
        float2 vf3 = unpack2(vp[3]);
        float2 vf4 = unpack2(vp[4]);

        ull a0, a1, a2, a3, a4, c0, c1, c2, c3, c4;

        #pragma unroll
        for (int l = 0; l < 10; l++) {
            const ulonglong2 p0 = row[l * 5 + 0];
            const ulonglong2 p1 = row[l * 5 + 1];
            const ulonglong2 p2 = row[l * 5 + 2];
            const ulonglong2 p3 = row[l * 5 + 3];
            const ulonglong2 p4 = row[l * 5 + 4];
            float vl;
            switch (l) {
                case 0: vl = vf0.x; break; case 1: vl = vf0.y; break;
                case 2: vl = vf1.x; break; case 3: vl = vf1.y; break;
                case 4: vl = vf2.x; break; case 5: vl = vf2.y; break;
                case 6: vl = vf3.x; break; case 7: vl = vf3.y; break;
                case 8: vl = vf4.x; break; default: vl = vf4.y; break;
            }
            const ull vl2 = pack2(vl, vl);
            if (l == 0) {
                a0 = mul2(vl2, p0.x); a1 = mul2(vl2, p0.y);
                a2 = mul2(vl2, p1.x); a3 = mul2(vl2, p1.y);
                a4 = mul2(vl2, p2.x);
                c0 = mul2(vl2, p2.y);
                c1 = mul2(vl2, p3.x); c2 = mul2(vl2, p3.y);
                c3 = mul2(vl2, p4.x); c4 = mul2(vl2, p4.y);
            } else {
                a0 = fma2(vl2, p0.x, a0); a1 = fma2(vl2, p0.y, a1);
                a2 = fma2(vl2, p1.x, a2); a3 = fma2(vl2, p1.y, a3);
                a4 = fma2(vl2, p2.x, a4);
                c0 = fma2(vl2, p2.y, c0);
                c1 = fma2(vl2, p3.x, c1); c2 = fma2(vl2, p3.y, c2);
                c3 = fma2(vl2, p4.x, c3); c4 = fma2(vl2, p4.y, c4);
            }
        }
        const ull fc2 = pack2(fcur.x, fcur.x);
        const ull fs2 = pack2(fcur.y, fcur.y);
        vp[0] = fma2(fs2, c0, mul2(fc2, a0));
        vp[1] = fma2(fs2, c1, mul2(fc2, a1));
        vp[2] = fma2(fs2, c2, mul2(fc2, a2));
        vp[3] = fma2(fs2, c3, mul2(fc2, a3));
        vp[4] = fma2(fs2, c4, mul2(fc2, a4));
        fcur = fnext;

        // prefetch site k+DIST into its ring slot (uniform commit keeps counts aligned)
        if (k + DIST < NSTEP) {
            const char* g = gsrc + (long)(k + DIST) * gstep;
            uint32_t dst = sbase + ((k + DIST) & (RING - 1)) * 800;
            cp16(dst + lane * 16, g + lane * 16);
            if (lane < 18) cp16(dst + (32 + lane) * 16, g + (32 + lane) * 16);
        }
        cp_commit();
    }

    if (fwd) {
        #pragma unroll
        for (int j = 0; j < 5; j++) g_V[(size_t)b * 5 + j] = vp[j];
    } else {
        #pragma unroll
        for (int j = 0; j < 5; j++) g_U[(size_t)b * 5 + j] = vp[j];
    }
}

// ---------------------------------------------------------------------------
// K3: s[b] = dot(v,u);  logits[b,c] = s[b] * w[c],  w[c] = sum_d OT[c,d,0]
// ---------------------------------------------------------------------------
__global__ void combine_kernel(const float* __restrict__ ot,
                               float* __restrict__ out) {
    __shared__ float ws[10];
    const int tid = threadIdx.x;
    if (tid < 10) {
        float w = 0.f;
        #pragma unroll
        for (int d = 0; d < 10; d++) w += ot[tid * 10 + d];
        ws[tid] = w;
    }
    __syncthreads();

    const int b = blockIdx.x * blockDim.x + tid;
    if (b >= BQ) return;
    float s = 0.f;
    #pragma unroll
    for (int j = 0; j < 5; j++) {
        float2 a = unpack2(g_V[(size_t)b * 5 + j]);
        float2 u = unpack2(g_U[(size_t)b * 5 + j]);
        s += a.x * u.x + a.y * u.y;
    }
    #pragma unroll
    for (int c = 0; c < 10; c++)
        out[(size_t)b * 10 + c] = s * ws[c];
}

// ---------------------------------------------------------------------------
extern "C" void kernel_launch(void* const* d_in, const int* in_sizes, int n_in,
                              void* d_out, int out_size) {
    const float* x          = (const float*)d_in[0];  // (8192, 784)
    const float* core_first = (const float*)d_in[1];  // (1, 2, 10)
    const float* cores_mid  = (const float*)d_in[2];  // (782, 10, 2, 10)
    const float* core_last  = (const float*)d_in[3];  // (10, 2, 1)
    const float* out_t      = (const float*)d_in[4];  // (10, 10, 1)
    float* out = (float*)d_out;                       // (8192, 10)

    dim3 fgrid((NQ + 31) / 32, BQ / 32);
    dim3 fblk(32, 8);
    feat_kernel<<<fgrid, fblk>>>(x);
    transpose_cores<<<NSITES, 200>>>(cores_mid);

    chain_kernel<<<128, 128>>>(core_first, cores_mid, core_last);

    combine_kernel<<<BQ / 256, 256>>>(out_t, out);
}